// round 3
// baseline (speedup 1.0000x reference)
#include <cuda_runtime.h>
#include <cuda_bf16.h>
#include <cstdint>

#define BSZ 8
#define NN  256
#define DD  256
#define LN_EPS 1e-5f

// ---------------- scratch (no allocation allowed) ----------------
__device__ float g_hihj[2 * BSZ * NN * DD];   // hi then hj, each [B*N, D]
__device__ float g_sc  [BSZ * NN * NN];       // scores -> softmax weights (in place)
__device__ float g_ctx [BSZ * NN * DD];
__device__ float g_proj[BSZ * NN * DD];

// ---------------- generic strided-batch GEMM: C = A @ W (+bias) ----------------
// A: [M, K] row-major, W: [K, Ncol] row-major, C: [M, Ncol].
// Tiles: 64x64x16, 256 threads, 4x4 register micro-tile.
__global__ void gemm_k(const float* __restrict__ A, long sA,
                       const float* __restrict__ W, long sW,
                       float* __restrict__ C, long sC,
                       const float* __restrict__ bias,
                       int M, int K, int Ncol)
{
    const int BK = 16;
    __shared__ float As[BK][64];   // transposed: As[k][m]
    __shared__ float Ws[BK][64];   // Ws[k][n]

    int z = blockIdx.z;
    A += (long)z * sA;  W += (long)z * sW;  C += (long)z * sC;

    int tid = threadIdx.x;
    int tx = tid & 15, ty = tid >> 4;
    int rowBase = blockIdx.x * 64;
    int colBase = blockIdx.y * 64;

    int ar  = tid >> 2;            // 0..63   (A tile row)
    int ac4 = (tid & 3) << 2;      // 0..12   (A tile col, float4)
    int wr  = tid >> 4;            // 0..15   (W tile row = k)
    int wc4 = (tid & 15) << 2;     // 0..60   (W tile col, float4)

    float acc[4][4] = {};

    for (int k0 = 0; k0 < K; k0 += BK) {
        float4 av = *(const float4*)&A[(long)(rowBase + ar) * K + k0 + ac4];
        float4 wv = *(const float4*)&W[(long)(k0 + wr) * Ncol + colBase + wc4];
        As[ac4 + 0][ar] = av.x;
        As[ac4 + 1][ar] = av.y;
        As[ac4 + 2][ar] = av.z;
        As[ac4 + 3][ar] = av.w;
        *(float4*)&Ws[wr][wc4] = wv;
        __syncthreads();

        #pragma unroll
        for (int kk = 0; kk < BK; kk++) {
            float4 a4 = *(const float4*)&As[kk][ty << 2];
            float4 w4 = *(const float4*)&Ws[kk][tx << 2];
            float aa[4] = {a4.x, a4.y, a4.z, a4.w};
            float ww[4] = {w4.x, w4.y, w4.z, w4.w};
            #pragma unroll
            for (int i = 0; i < 4; i++)
                #pragma unroll
                for (int j = 0; j < 4; j++)
                    acc[i][j] += aa[i] * ww[j];
        }
        __syncthreads();
    }

    #pragma unroll
    for (int i = 0; i < 4; i++) {
        int row = rowBase + (ty << 2) + i;
        int col = colBase + (tx << 2);
        float4 o = {acc[i][0], acc[i][1], acc[i][2], acc[i][3]};
        if (bias) {
            o.x += bias[col + 0]; o.y += bias[col + 1];
            o.z += bias[col + 2]; o.w += bias[col + 3];
        }
        *(float4*)&C[(long)row * Ncol + col] = o;
    }
}

// ---------------- pairwise relu score kernel ----------------
// scores[b,n,m] = sum_d relu(hi[b,n,d] + hj[b,m,d] + b1[d]) * W2[d] + b2
// diag (n==m) forced to 0 before softmax (matches reference).
__global__ void scores_k(const float* __restrict__ b1,
                         const float* __restrict__ W2,
                         const float* __restrict__ b2)
{
    const int DK = 32;
    __shared__ float His[DK][68];   // [d][n], pad 68 keeps float4 alignment, reduces store conflicts
    __shared__ float Hjs[DK][68];   // [d][m]
    __shared__ float b1s[DK];
    __shared__ float w2s[DK];

    int b = blockIdx.z;
    int mBase = blockIdx.x * 64;
    int nBase = blockIdx.y * 64;
    int tid = threadIdx.x;
    int tx = tid & 15, ty = tid >> 4;

    const float* hi = g_hihj + (long)b * NN * DD;
    const float* hj = g_hihj + (long)BSZ * NN * DD + (long)b * NN * DD;

    float acc[4][4] = {};
    const float b2v = b2[0];

    for (int d0 = 0; d0 < DD; d0 += DK) {
        #pragma unroll
        for (int u = 0; u < 2; u++) {
            int f  = u * 256 + tid;       // float4 index over 64x32 tile
            int r  = f >> 3;              // 0..63
            int c4 = (f & 7) << 2;        // 0..28
            float4 hv = *(const float4*)&hi[(long)(nBase + r) * DD + d0 + c4];
            float4 jv = *(const float4*)&hj[(long)(mBase + r) * DD + d0 + c4];
            His[c4 + 0][r] = hv.x; His[c4 + 1][r] = hv.y;
            His[c4 + 2][r] = hv.z; His[c4 + 3][r] = hv.w;
            Hjs[c4 + 0][r] = jv.x; Hjs[c4 + 1][r] = jv.y;
            Hjs[c4 + 2][r] = jv.z; Hjs[c4 + 3][r] = jv.w;
        }
        if (tid < DK) { b1s[tid] = b1[d0 + tid]; w2s[tid] = W2[d0 + tid]; }
        __syncthreads();

        #pragma unroll 4
        for (int d = 0; d < DK; d++) {
            float4 a4 = *(const float4*)&His[d][ty << 2];
            float4 c4 = *(const float4*)&Hjs[d][tx << 2];
            float bias = b1s[d], w = w2s[d];
            float ab[4] = {a4.x + bias, a4.y + bias, a4.z + bias, a4.w + bias};
            float bb[4] = {c4.x, c4.y, c4.z, c4.w};
            #pragma unroll
            for (int i = 0; i < 4; i++)
                #pragma unroll
                for (int j = 0; j < 4; j++)
                    acc[i][j] += fmaxf(ab[i] + bb[j], 0.0f) * w;
        }
        __syncthreads();
    }

    float* sc = g_sc + (long)b * NN * NN;
    #pragma unroll
    for (int i = 0; i < 4; i++) {
        int n = nBase + (ty << 2) + i;
        int m = mBase + (tx << 2);
        float4 o;
        o.x = (n == m + 0) ? 0.0f : acc[i][0] + b2v;
        o.y = (n == m + 1) ? 0.0f : acc[i][1] + b2v;
        o.z = (n == m + 2) ? 0.0f : acc[i][2] + b2v;
        o.w = (n == m + 3) ? 0.0f : acc[i][3] + b2v;
        *(float4*)&sc[(long)n * NN + m] = o;
    }
}

// ---------------- softmax over m, in place on g_sc ----------------
__global__ void softmax_k()
{
    __shared__ float red[8];
    int row = blockIdx.x;          // b*N + n
    int tid = threadIdx.x;
    int wid = tid >> 5, lane = tid & 31;

    float* sc = g_sc + (long)row * NN;
    float v = sc[tid];

    float mv = v;
    #pragma unroll
    for (int o = 16; o > 0; o >>= 1) mv = fmaxf(mv, __shfl_xor_sync(0xffffffffu, mv, o));
    if (lane == 0) red[wid] = mv;
    __syncthreads();
    float mx = red[0];
    #pragma unroll
    for (int w = 1; w < 8; w++) mx = fmaxf(mx, red[w]);

    float e = __expf(v - mx);
    float s = e;
    #pragma unroll
    for (int o = 16; o > 0; o >>= 1) s += __shfl_xor_sync(0xffffffffu, s, o);
    __syncthreads();
    if (lane == 0) red[wid] = s;
    __syncthreads();
    float sum = 0.0f;
    #pragma unroll
    for (int w = 0; w < 8; w++) sum += red[w];

    sc[tid] = e * (1.0f / sum);
}

// ---------------- LayerNorm + residual ----------------
__global__ void ln_res_k(const float* __restrict__ x,
                         const float* __restrict__ gamma,
                         const float* __restrict__ beta,
                         float* __restrict__ out)
{
    __shared__ float red[8];
    int row = blockIdx.x;
    int tid = threadIdx.x;
    int wid = tid >> 5, lane = tid & 31;

    float p = g_proj[(long)row * DD + tid];

    float s = p;
    #pragma unroll
    for (int o = 16; o > 0; o >>= 1) s += __shfl_xor_sync(0xffffffffu, s, o);
    if (lane == 0) red[wid] = s;
    __syncthreads();
    float tot = 0.0f;
    #pragma unroll
    for (int w = 0; w < 8; w++) tot += red[w];
    float mean = tot * (1.0f / DD);

    float dv = p - mean;
    float q = dv * dv;
    #pragma unroll
    for (int o = 16; o > 0; o >>= 1) q += __shfl_xor_sync(0xffffffffu, q, o);
    __syncthreads();
    if (lane == 0) red[wid] = q;
    __syncthreads();
    float tq = 0.0f;
    #pragma unroll
    for (int w = 0; w < 8; w++) tq += red[w];
    float var = tq * (1.0f / DD);

    float inv = rsqrtf(var + LN_EPS);
    out[(long)row * DD + tid] = x[(long)row * DD + tid] + dv * inv * gamma[tid] + beta[tid];
}

// ---------------- launch ----------------
extern "C" void kernel_launch(void* const* d_in, const int* in_sizes, int n_in,
                              void* d_out, int out_size)
{
    const float* x     = (const float*)d_in[0];  // [B,N,D]
    const float* W1    = (const float*)d_in[1];  // [2D,D]
    const float* b1    = (const float*)d_in[2];  // [D]
    const float* W2    = (const float*)d_in[3];  // [D,1]
    const float* b2    = (const float*)d_in[4];  // [1]
    const float* Wp    = (const float*)d_in[5];  // [D,D]
    const float* bp    = (const float*)d_in[6];  // [D]
    const float* gamma = (const float*)d_in[7];  // [D]
    const float* beta  = (const float*)d_in[8];  // [D]
    float* out = (float*)d_out;

    float *hihj, *sc, *ctx, *proj;
    cudaGetSymbolAddress((void**)&hihj, g_hihj);
    cudaGetSymbolAddress((void**)&sc,   g_sc);
    cudaGetSymbolAddress((void**)&ctx,  g_ctx);
    cudaGetSymbolAddress((void**)&proj, g_proj);

    // 1) hi = x @ W1[:D], hj = x @ W1[D:]  (z picks the W1 half and output slab)
    gemm_k<<<dim3((BSZ * NN) / 64, DD / 64, 2), 256>>>(
        x, 0L, W1, (long)DD * DD, hihj, (long)BSZ * NN * DD, nullptr,
        BSZ * NN, DD, DD);

    // 2) pairwise relu scores (+b2, diag=0)
    scores_k<<<dim3(NN / 64, NN / 64, BSZ), 256>>>(b1, W2, b2);

    // 3) softmax over m (in place)
    softmax_k<<<BSZ * NN, 256>>>();

    // 4) ctx[b] = weights[b] @ x[b]   (batched over z)
    gemm_k<<<dim3(NN / 64, DD / 64, BSZ), 256>>>(
        sc, (long)NN * NN, x, (long)NN * DD, ctx, (long)NN * DD, nullptr,
        NN, NN, DD);

    // 5) proj = ctx @ Wp + bp
    gemm_k<<<dim3((BSZ * NN) / 64, DD / 64, 1), 256>>>(
        ctx, 0L, Wp, 0L, proj, 0L, bp,
        BSZ * NN, DD, DD);

    // 6) out = x + LN(proj)
    ln_res_k<<<BSZ * NN, 256>>>(x, gamma, beta, out);
}

// round 4
// speedup vs baseline: 1.0234x; 1.0234x over previous
#include <cuda_runtime.h>
#include <cuda_bf16.h>
#include <cstdint>

#define BSZ 8
#define NN  256
#define DD  256
#define LN_EPS 1e-5f

// ---------------- scratch (no allocation allowed) ----------------
__device__ __align__(16) float g_hihj[2 * BSZ * NN * DD];   // hi+0.5*b1, hj+0.5*b1
__device__ __align__(16) float g_sc  [BSZ * NN * NN];       // scores -> weights (in place)
__device__ __align__(16) float g_ctx [BSZ * NN * DD];
__device__ __align__(16) float g_proj[BSZ * NN * DD];

// ---------------- f32x2 helpers (exact fp32, packed pipe) ----------------
typedef unsigned long long u64;

__device__ __forceinline__ u64 dup2(float x) {
    u64 r; asm("mov.b64 %0, {%1, %2};" : "=l"(r) : "f"(x), "f"(x)); return r;
}
__device__ __forceinline__ void fma2(u64& a, u64 b, u64 c) {
    asm("fma.rn.f32x2 %0, %1, %2, %0;" : "+l"(a) : "l"(b), "l"(c));
}
__device__ __forceinline__ u64 add2(u64 a, u64 b) {
    u64 r; asm("add.rn.f32x2 %0, %1, %2;" : "=l"(r) : "l"(a), "l"(b)); return r;
}
__device__ __forceinline__ void unpack2(u64 v, float& lo, float& hi) {
    asm("mov.b64 {%0, %1}, %2;" : "=f"(lo), "=f"(hi) : "l"(v));
}
__device__ __forceinline__ u64 relu2(u64 v) {
    float lo, hi;
    asm("mov.b64 {%0, %1}, %2;" : "=f"(lo), "=f"(hi) : "l"(v));
    lo = fmaxf(lo, 0.0f); hi = fmaxf(hi, 0.0f);
    u64 r; asm("mov.b64 %0, {%1, %2};" : "=l"(r) : "f"(lo), "f"(hi));
    return r;
}

// ---------------- GEMM: C = A @ W (+ bias*bscale) ----------------
// Tile 64(M) x 32(N) x 32(K), 256 threads, micro 4x2 (row-pair packed f32x2),
// double-buffered smem, one __syncthreads per K-chunk.
__global__ void gemm_k(const float* __restrict__ A, long sA,
                       const float* __restrict__ W, long sW,
                       float* __restrict__ C, long sC,
                       const float* __restrict__ bias, float bscale,
                       int K, int Ncol)
{
    const int BK = 32;
    __shared__ __align__(16) float As[2][BK][64];   // transposed: As[k][m]
    __shared__ __align__(16) float Ws[2][BK][32];   // Ws[k][n]

    int z = blockIdx.z;
    A += (long)z * sA;  W += (long)z * sW;  C += (long)z * sC;

    int tid = threadIdx.x;
    int tx = tid & 15, ty = tid >> 4;
    int rowBase = blockIdx.x * 64;
    int colBase = blockIdx.y * 32;

    // loader indices
    int ar0 = tid >> 3;            int ac0 = (tid & 7) << 2;    // A float4 #0
    int ar1 = (tid + 256) >> 3;    int ac1 = ac0;               // A float4 #1
    int wr  = tid >> 3;            int wc  = (tid & 7) << 2;    // W float4

    u64 acc00 = 0, acc01 = 0, acc10 = 0, acc11 = 0;

    // prologue: chunk 0
    float4 av0 = *(const float4*)&A[(long)(rowBase + ar0) * K + ac0];
    float4 av1 = *(const float4*)&A[(long)(rowBase + ar1) * K + ac1];
    float4 wv  = *(const float4*)&W[(long)wr * Ncol + colBase + wc];
    {
        As[0][ac0 + 0][ar0] = av0.x; As[0][ac0 + 1][ar0] = av0.y;
        As[0][ac0 + 2][ar0] = av0.z; As[0][ac0 + 3][ar0] = av0.w;
        As[0][ac1 + 0][ar1] = av1.x; As[0][ac1 + 1][ar1] = av1.y;
        As[0][ac1 + 2][ar1] = av1.z; As[0][ac1 + 3][ar1] = av1.w;
        *(float4*)&Ws[0][wr][wc] = wv;
    }
    __syncthreads();

    int buf = 0;
    for (int k0 = 0; k0 < K; k0 += BK) {
        bool more = (k0 + BK) < K;
        if (more) {
            av0 = *(const float4*)&A[(long)(rowBase + ar0) * K + k0 + BK + ac0];
            av1 = *(const float4*)&A[(long)(rowBase + ar1) * K + k0 + BK + ac1];
            wv  = *(const float4*)&W[(long)(k0 + BK + wr) * Ncol + colBase + wc];
        }

        #pragma unroll
        for (int kk = 0; kk < BK; kk++) {
            ulonglong2 a = *(const ulonglong2*)&As[buf][kk][ty << 2];
            float2 w = *(const float2*)&Ws[buf][kk][tx << 1];
            u64 wd0 = dup2(w.x), wd1 = dup2(w.y);
            fma2(acc00, a.x, wd0); fma2(acc01, a.x, wd1);
            fma2(acc10, a.y, wd0); fma2(acc11, a.y, wd1);
        }

        if (more) {
            int nb = buf ^ 1;
            As[nb][ac0 + 0][ar0] = av0.x; As[nb][ac0 + 1][ar0] = av0.y;
            As[nb][ac0 + 2][ar0] = av0.z; As[nb][ac0 + 3][ar0] = av0.w;
            As[nb][ac1 + 0][ar1] = av1.x; As[nb][ac1 + 1][ar1] = av1.y;
            As[nb][ac1 + 2][ar1] = av1.z; As[nb][ac1 + 3][ar1] = av1.w;
            *(float4*)&Ws[nb][wr][wc] = wv;
        }
        __syncthreads();
        buf ^= 1;
    }

    int row0 = rowBase + (ty << 2);
    int col  = colBase + (tx << 1);
    float bx = 0.0f, by = 0.0f;
    if (bias) { bx = bias[col] * bscale; by = bias[col + 1] * bscale; }

    float l0, h0, l1, h1;
    unpack2(acc00, l0, h0); unpack2(acc01, l1, h1);
    *(float2*)&C[(long)(row0 + 0) * Ncol + col] = make_float2(l0 + bx, l1 + by);
    *(float2*)&C[(long)(row0 + 1) * Ncol + col] = make_float2(h0 + bx, h1 + by);
    unpack2(acc10, l0, h0); unpack2(acc11, l1, h1);
    *(float2*)&C[(long)(row0 + 2) * Ncol + col] = make_float2(l0 + bx, l1 + by);
    *(float2*)&C[(long)(row0 + 3) * Ncol + col] = make_float2(h0 + bx, h1 + by);
}

// ---------------- pairwise relu score kernel ----------------
// scores[b,n,m] = sum_d relu(hi'[n,d] + hj'[m,d]) * W2[d] + b2   (b1 pre-folded)
// Tile: 64 n-rows x 32 m-cols, 256 threads, micro 4x2 (n-pair packed).
__global__ void scores_k(const float* __restrict__ W2,
                         const float* __restrict__ b2)
{
    const int DK = 32;
    __shared__ __align__(16) float His[2][DK][64];   // [d][n]
    __shared__ __align__(16) float Hjs[2][DK][32];   // [d][m]
    __shared__ float w2s[DD];

    int b = blockIdx.z;
    int mBase = blockIdx.x * 32;
    int nBase = blockIdx.y * 64;
    int tid = threadIdx.x;
    int tx = tid & 15, ty = tid >> 4;

    const float* hi = g_hihj + (long)b * NN * DD;
    const float* hj = g_hihj + (long)BSZ * NN * DD + (long)b * NN * DD;

    w2s[tid] = W2[tid];   // 256 threads cover D=256

    int ar0 = tid >> 3;          int ac0 = (tid & 7) << 2;
    int ar1 = (tid + 256) >> 3;
    int jr  = tid >> 3;          int jc  = (tid & 7) << 2;

    u64 acc00 = 0, acc01 = 0, acc10 = 0, acc11 = 0;

    float4 iv0 = *(const float4*)&hi[(long)(nBase + ar0) * DD + ac0];
    float4 iv1 = *(const float4*)&hi[(long)(nBase + ar1) * DD + ac0];
    float4 jv  = *(const float4*)&hj[(long)(mBase + jr) * DD + jc];
    {
        His[0][ac0 + 0][ar0] = iv0.x; His[0][ac0 + 1][ar0] = iv0.y;
        His[0][ac0 + 2][ar0] = iv0.z; His[0][ac0 + 3][ar0] = iv0.w;
        His[0][ac0 + 0][ar1] = iv1.x; His[0][ac0 + 1][ar1] = iv1.y;
        His[0][ac0 + 2][ar1] = iv1.z; His[0][ac0 + 3][ar1] = iv1.w;
        Hjs[0][jc + 0][jr] = jv.x; Hjs[0][jc + 1][jr] = jv.y;
        Hjs[0][jc + 2][jr] = jv.z; Hjs[0][jc + 3][jr] = jv.w;
    }
    __syncthreads();

    int buf = 0;
    for (int d0 = 0; d0 < DD; d0 += DK) {
        bool more = (d0 + DK) < DD;
        if (more) {
            iv0 = *(const float4*)&hi[(long)(nBase + ar0) * DD + d0 + DK + ac0];
            iv1 = *(const float4*)&hi[(long)(nBase + ar1) * DD + d0 + DK + ac0];
            jv  = *(const float4*)&hj[(long)(mBase + jr) * DD + d0 + DK + jc];
        }

        #pragma unroll
        for (int d = 0; d < DK; d++) {
            ulonglong2 a = *(const ulonglong2*)&His[buf][d][ty << 2];
            float2 bv = *(const float2*)&Hjs[buf][d][tx << 1];
            u64 bd0 = dup2(bv.x), bd1 = dup2(bv.y);
            u64 wd  = dup2(w2s[d0 + d]);
            fma2(acc00, relu2(add2(a.x, bd0)), wd);
            fma2(acc01, relu2(add2(a.x, bd1)), wd);
            fma2(acc10, relu2(add2(a.y, bd0)), wd);
            fma2(acc11, relu2(add2(a.y, bd1)), wd);
        }

        if (more) {
            int nb = buf ^ 1;
            His[nb][ac0 + 0][ar0] = iv0.x; His[nb][ac0 + 1][ar0] = iv0.y;
            His[nb][ac0 + 2][ar0] = iv0.z; His[nb][ac0 + 3][ar0] = iv0.w;
            His[nb][ac0 + 0][ar1] = iv1.x; His[nb][ac0 + 1][ar1] = iv1.y;
            His[nb][ac0 + 2][ar1] = iv1.z; His[nb][ac0 + 3][ar1] = iv1.w;
            Hjs[nb][jc + 0][jr] = jv.x; Hjs[nb][jc + 1][jr] = jv.y;
            Hjs[nb][jc + 2][jr] = jv.z; Hjs[nb][jc + 3][jr] = jv.w;
        }
        __syncthreads();
        buf ^= 1;
    }

    const float b2v = b2[0];
    float* sc = g_sc + (long)b * NN * NN;
    int n0 = nBase + (ty << 2);
    int m0 = mBase + (tx << 1);

    float l0, h0, l1, h1;
    unpack2(acc00, l0, h0); unpack2(acc01, l1, h1);
    *(float2*)&sc[(long)(n0 + 0) * NN + m0] =
        make_float2((n0 + 0 == m0) ? 0.0f : l0 + b2v, (n0 + 0 == m0 + 1) ? 0.0f : l1 + b2v);
    *(float2*)&sc[(long)(n0 + 1) * NN + m0] =
        make_float2((n0 + 1 == m0) ? 0.0f : h0 + b2v, (n0 + 1 == m0 + 1) ? 0.0f : h1 + b2v);
    unpack2(acc10, l0, h0); unpack2(acc11, l1, h1);
    *(float2*)&sc[(long)(n0 + 2) * NN + m0] =
        make_float2((n0 + 2 == m0) ? 0.0f : l0 + b2v, (n0 + 2 == m0 + 1) ? 0.0f : l1 + b2v);
    *(float2*)&sc[(long)(n0 + 3) * NN + m0] =
        make_float2((n0 + 3 == m0) ? 0.0f : h0 + b2v, (n0 + 3 == m0 + 1) ? 0.0f : h1 + b2v);
}

// ---------------- softmax over m, in place on g_sc ----------------
__global__ void softmax_k()
{
    __shared__ float red[8];
    int row = blockIdx.x;          // b*N + n
    int tid = threadIdx.x;
    int wid = tid >> 5, lane = tid & 31;

    float* sc = g_sc + (long)row * NN;
    float v = sc[tid];

    float mv = v;
    #pragma unroll
    for (int o = 16; o > 0; o >>= 1) mv = fmaxf(mv, __shfl_xor_sync(0xffffffffu, mv, o));
    if (lane == 0) red[wid] = mv;
    __syncthreads();
    float mx = red[0];
    #pragma unroll
    for (int w = 1; w < 8; w++) mx = fmaxf(mx, red[w]);

    float e = __expf(v - mx);
    float s = e;
    #pragma unroll
    for (int o = 16; o > 0; o >>= 1) s += __shfl_xor_sync(0xffffffffu, s, o);
    __syncthreads();
    if (lane == 0) red[wid] = s;
    __syncthreads();
    float sum = 0.0f;
    #pragma unroll
    for (int w = 0; w < 8; w++) sum += red[w];

    sc[tid] = e * (1.0f / sum);
}

// ---------------- LayerNorm + residual ----------------
__global__ void ln_res_k(const float* __restrict__ x,
                         const float* __restrict__ gamma,
                         const float* __restrict__ beta,
                         float* __restrict__ out)
{
    __shared__ float red[8];
    int row = blockIdx.x;
    int tid = threadIdx.x;
    int wid = tid >> 5, lane = tid & 31;

    float p = g_proj[(long)row * DD + tid];

    float s = p;
    #pragma unroll
    for (int o = 16; o > 0; o >>= 1) s += __shfl_xor_sync(0xffffffffu, s, o);
    if (lane == 0) red[wid] = s;
    __syncthreads();
    float tot = 0.0f;
    #pragma unroll
    for (int w = 0; w < 8; w++) tot += red[w];
    float mean = tot * (1.0f / DD);

    float dv = p - mean;
    float q = dv * dv;
    #pragma unroll
    for (int o = 16; o > 0; o >>= 1) q += __shfl_xor_sync(0xffffffffu, q, o);
    __syncthreads();
    if (lane == 0) red[wid] = q;
    __syncthreads();
    float tq = 0.0f;
    #pragma unroll
    for (int w = 0; w < 8; w++) tq += red[w];
    float var = tq * (1.0f / DD);

    float inv = rsqrtf(var + LN_EPS);
    out[(long)row * DD + tid] = x[(long)row * DD + tid] + dv * inv * gamma[tid] + beta[tid];
}

// ---------------- launch ----------------
extern "C" void kernel_launch(void* const* d_in, const int* in_sizes, int n_in,
                              void* d_out, int out_size)
{
    const float* x     = (const float*)d_in[0];  // [B,N,D]
    const float* W1    = (const float*)d_in[1];  // [2D,D]
    const float* b1    = (const float*)d_in[2];  // [D]
    const float* W2    = (const float*)d_in[3];  // [D,1]
    const float* b2    = (const float*)d_in[4];  // [1]
    const float* Wp    = (const float*)d_in[5];  // [D,D]
    const float* bp    = (const float*)d_in[6];  // [D]
    const float* gamma = (const float*)d_in[7];  // [D]
    const float* beta  = (const float*)d_in[8];  // [D]
    float* out = (float*)d_out;

    float *hihj, *sc, *ctx, *proj;
    cudaGetSymbolAddress((void**)&hihj, g_hihj);
    cudaGetSymbolAddress((void**)&sc,   g_sc);
    cudaGetSymbolAddress((void**)&ctx,  g_ctx);
    cudaGetSymbolAddress((void**)&proj, g_proj);

    // 1) hi' = x @ W1[:D] + 0.5*b1 ; hj' = x @ W1[D:] + 0.5*b1
    //    (z picks W1 half + output slab; 0.5*b1 on each half so hi'+hj' carries full b1)
    gemm_k<<<dim3((BSZ * NN) / 64, DD / 32, 2), 256>>>(
        x, 0L, W1, (long)DD * DD, hihj, (long)BSZ * NN * DD,
        b1, 0.5f, DD, DD);

    // 2) pairwise relu scores (+b2, diag=0)
    scores_k<<<dim3(NN / 32, NN / 64, BSZ), 256>>>(W2, b2);

    // 3) softmax over m (in place)
    softmax_k<<<BSZ * NN, 256>>>();

    // 4) ctx[b] = weights[b] @ x[b]
    gemm_k<<<dim3(NN / 64, DD / 32, BSZ), 256>>>(
        sc, (long)NN * NN, x, (long)NN * DD, ctx, (long)NN * DD,
        nullptr, 0.0f, NN, DD);

    // 5) proj = ctx @ Wp + bp
    gemm_k<<<dim3((BSZ * NN) / 64, DD / 32, 1), 256>>>(
        ctx, 0L, Wp, 0L, proj, 0L,
        bp, 1.0f, DD, DD);

    // 6) out = x + LN(proj)
    ln_res_k<<<BSZ * NN, 256>>>(x, gamma, beta, out);
}

// round 5
// speedup vs baseline: 1.0507x; 1.0266x over previous
#include <cuda_runtime.h>
#include <cuda_bf16.h>
#include <cstdint>

#define BSZ 8
#define NN  256
#define DD  256
#define LN_EPS 1e-5f

// ---------------- scratch (no allocation allowed) ----------------
__device__ __align__(16) float g_hihj[2 * BSZ * NN * DD];   // hi+0.5*b1, hj+0.5*b1
__device__ __align__(16) float g_sc  [BSZ * NN * NN];       // scores -> weights (in place)
__device__ __align__(16) float g_ctx [BSZ * NN * DD];
__device__ __align__(16) float g_proj[BSZ * NN * DD];

// ---------------- f32x2 helpers (exact fp32, packed pipe) ----------------
typedef unsigned long long u64;

__device__ __forceinline__ u64 dup2(float x) {
    u64 r; asm("mov.b64 %0, {%1, %2};" : "=l"(r) : "f"(x), "f"(x)); return r;
}
__device__ __forceinline__ void fma2(u64& a, u64 b, u64 c) {
    asm("fma.rn.f32x2 %0, %1, %2, %0;" : "+l"(a) : "l"(b), "l"(c));
}
__device__ __forceinline__ u64 add2(u64 a, u64 b) {
    u64 r; asm("add.rn.f32x2 %0, %1, %2;" : "=l"(r) : "l"(a), "l"(b)); return r;
}
__device__ __forceinline__ void unpack2(u64 v, float& lo, float& hi) {
    asm("mov.b64 {%0, %1}, %2;" : "=f"(lo), "=f"(hi) : "l"(v));
}
__device__ __forceinline__ u64 relu2(u64 v) {
    float lo, hi;
    asm("mov.b64 {%0, %1}, %2;" : "=f"(lo), "=f"(hi) : "l"(v));
    lo = fmaxf(lo, 0.0f); hi = fmaxf(hi, 0.0f);
    u64 r; asm("mov.b64 %0, {%1, %2};" : "=l"(r) : "f"(lo), "f"(hi));
    return r;
}

// ---------------- GEMM: C = A @ W (+ bias*bscale) ----------------
// Tile 64x64x16, 128 threads, micro-tile 8(rows, as 4 f32x2 pairs) x 4(cols).
// Double-buffered smem, one sync per K-chunk.
__global__ void __launch_bounds__(128) gemm_k(
    const float* __restrict__ A, long sA,
    const float* __restrict__ W, long sW,
    float* __restrict__ C, long sC,
    const float* __restrict__ bias, float bscale,
    int K, int Ncol)
{
    const int BK = 16;
    __shared__ __align__(16) float As[2][BK][64];   // transposed: As[k][m]
    __shared__ __align__(16) float Ws[2][BK][64];   // Ws[k][n]

    int z = blockIdx.z;
    A += (long)z * sA;  W += (long)z * sW;  C += (long)z * sC;

    int tid = threadIdx.x;
    int tx  = tid & 15;        // col group: cols tx*4 .. +3
    int tyg = tid >> 4;        // 0..7 row group: rows tyg*8 .. +7
    int rowBase = blockIdx.x * 64;
    int colBase = blockIdx.y * 64;

    // loader indices: 64x16 A tile = 256 float4; 16x64 W tile = 256 float4; 2 each
    int f1 = tid + 128;
    int ar0 = tid >> 2, ac0 = (tid & 3) << 2;
    int ar1 = f1  >> 2, ac1 = (f1  & 3) << 2;
    int wr0 = tid >> 4, wc0 = (tid & 15) << 2;
    int wr1 = f1  >> 4, wc1 = (f1  & 15) << 2;

    u64 acc[4][4] = {};

    float4 a0 = *(const float4*)&A[(long)(rowBase + ar0) * K + ac0];
    float4 a1 = *(const float4*)&A[(long)(rowBase + ar1) * K + ac1];
    float4 w0 = *(const float4*)&W[(long)wr0 * Ncol + colBase + wc0];
    float4 w1 = *(const float4*)&W[(long)wr1 * Ncol + colBase + wc1];
    {
        As[0][ac0 + 0][ar0] = a0.x; As[0][ac0 + 1][ar0] = a0.y;
        As[0][ac0 + 2][ar0] = a0.z; As[0][ac0 + 3][ar0] = a0.w;
        As[0][ac1 + 0][ar1] = a1.x; As[0][ac1 + 1][ar1] = a1.y;
        As[0][ac1 + 2][ar1] = a1.z; As[0][ac1 + 3][ar1] = a1.w;
        *(float4*)&Ws[0][wr0][wc0] = w0;
        *(float4*)&Ws[0][wr1][wc1] = w1;
    }
    __syncthreads();

    int buf = 0;
    for (int k0 = 0; k0 < K; k0 += BK) {
        bool more = (k0 + BK) < K;
        if (more) {
            a0 = *(const float4*)&A[(long)(rowBase + ar0) * K + k0 + BK + ac0];
            a1 = *(const float4*)&A[(long)(rowBase + ar1) * K + k0 + BK + ac1];
            w0 = *(const float4*)&W[(long)(k0 + BK + wr0) * Ncol + colBase + wc0];
            w1 = *(const float4*)&W[(long)(k0 + BK + wr1) * Ncol + colBase + wc1];
        }

        #pragma unroll
        for (int kk = 0; kk < BK; kk++) {
            ulonglong2 aL = *(const ulonglong2*)&As[buf][kk][(tyg << 3) + 0];
            ulonglong2 aH = *(const ulonglong2*)&As[buf][kk][(tyg << 3) + 4];
            float4 wv = *(const float4*)&Ws[buf][kk][tx << 2];
            u64 ap[4] = {aL.x, aL.y, aH.x, aH.y};
            u64 wd[4] = {dup2(wv.x), dup2(wv.y), dup2(wv.z), dup2(wv.w)};
            #pragma unroll
            for (int p = 0; p < 4; p++)
                #pragma unroll
                for (int j = 0; j < 4; j++)
                    fma2(acc[p][j], ap[p], wd[j]);
        }

        if (more) {
            int nb = buf ^ 1;
            As[nb][ac0 + 0][ar0] = a0.x; As[nb][ac0 + 1][ar0] = a0.y;
            As[nb][ac0 + 2][ar0] = a0.z; As[nb][ac0 + 3][ar0] = a0.w;
            As[nb][ac1 + 0][ar1] = a1.x; As[nb][ac1 + 1][ar1] = a1.y;
            As[nb][ac1 + 2][ar1] = a1.z; As[nb][ac1 + 3][ar1] = a1.w;
            *(float4*)&Ws[nb][wr0][wc0] = w0;
            *(float4*)&Ws[nb][wr1][wc1] = w1;
        }
        __syncthreads();
        buf ^= 1;
    }

    int row0 = rowBase + (tyg << 3);
    int col  = colBase + (tx << 2);
    float4 bv = make_float4(0.f, 0.f, 0.f, 0.f);
    if (bias) {
        bv = *(const float4*)&bias[col];
        bv.x *= bscale; bv.y *= bscale; bv.z *= bscale; bv.w *= bscale;
    }

    #pragma unroll
    for (int p = 0; p < 4; p++) {
        float e0, o0, e1, o1, e2, o2, e3, o3;
        unpack2(acc[p][0], e0, o0); unpack2(acc[p][1], e1, o1);
        unpack2(acc[p][2], e2, o2); unpack2(acc[p][3], e3, o3);
        *(float4*)&C[(long)(row0 + 2 * p + 0) * Ncol + col] =
            make_float4(e0 + bv.x, e1 + bv.y, e2 + bv.z, e3 + bv.w);
        *(float4*)&C[(long)(row0 + 2 * p + 1) * Ncol + col] =
            make_float4(o0 + bv.x, o1 + bv.y, o2 + bv.z, o3 + bv.w);
    }
}

// ---------------- pairwise relu score kernel ----------------
// scores[b,n,m] = sum_d relu(hi'[n,d] + hj'[m,d]) * W2[d] + b2   (b1 pre-folded)
// Tile 64(n) x 64(m) x 16(d), 128 threads, micro 8x4 (n-pairs packed f32x2).
__global__ void __launch_bounds__(128) scores_k(
    const float* __restrict__ W2,
    const float* __restrict__ b2)
{
    const int DK = 16;
    __shared__ __align__(16) float His[2][DK][64];   // [d][n]
    __shared__ __align__(16) float Hjs[2][DK][64];   // [d][m]
    __shared__ float w2s[DD];

    int b = blockIdx.z;
    int mBase = blockIdx.x * 64;
    int nBase = blockIdx.y * 64;
    int tid = threadIdx.x;
    int tx  = tid & 15;
    int tyg = tid >> 4;

    const float* hi = g_hihj + (long)b * NN * DD;
    const float* hj = g_hihj + (long)BSZ * NN * DD + (long)b * NN * DD;

    w2s[tid]       = W2[tid];
    w2s[tid + 128] = W2[tid + 128];

    int f1 = tid + 128;
    int ar0 = tid >> 2, ac0 = (tid & 3) << 2;
    int ar1 = f1  >> 2, ac1 = (f1  & 3) << 2;

    u64 acc[4][4] = {};

    float4 i0 = *(const float4*)&hi[(long)(nBase + ar0) * DD + ac0];
    float4 i1 = *(const float4*)&hi[(long)(nBase + ar1) * DD + ac1];
    float4 j0 = *(const float4*)&hj[(long)(mBase + ar0) * DD + ac0];
    float4 j1 = *(const float4*)&hj[(long)(mBase + ar1) * DD + ac1];
    {
        His[0][ac0 + 0][ar0] = i0.x; His[0][ac0 + 1][ar0] = i0.y;
        His[0][ac0 + 2][ar0] = i0.z; His[0][ac0 + 3][ar0] = i0.w;
        His[0][ac1 + 0][ar1] = i1.x; His[0][ac1 + 1][ar1] = i1.y;
        His[0][ac1 + 2][ar1] = i1.z; His[0][ac1 + 3][ar1] = i1.w;
        Hjs[0][ac0 + 0][ar0] = j0.x; Hjs[0][ac0 + 1][ar0] = j0.y;
        Hjs[0][ac0 + 2][ar0] = j0.z; Hjs[0][ac0 + 3][ar0] = j0.w;
        Hjs[0][ac1 + 0][ar1] = j1.x; Hjs[0][ac1 + 1][ar1] = j1.y;
        Hjs[0][ac1 + 2][ar1] = j1.z; Hjs[0][ac1 + 3][ar1] = j1.w;
    }
    __syncthreads();

    int buf = 0;
    for (int d0 = 0; d0 < DD; d0 += DK) {
        bool more = (d0 + DK) < DD;
        if (more) {
            i0 = *(const float4*)&hi[(long)(nBase + ar0) * DD + d0 + DK + ac0];
            i1 = *(const float4*)&hi[(long)(nBase + ar1) * DD + d0 + DK + ac1];
            j0 = *(const float4*)&hj[(long)(mBase + ar0) * DD + d0 + DK + ac0];
            j1 = *(const float4*)&hj[(long)(mBase + ar1) * DD + d0 + DK + ac1];
        }

        #pragma unroll
        for (int kk = 0; kk < DK; kk++) {
            ulonglong2 aL = *(const ulonglong2*)&His[buf][kk][(tyg << 3) + 0];
            ulonglong2 aH = *(const ulonglong2*)&His[buf][kk][(tyg << 3) + 4];
            float4 jv = *(const float4*)&Hjs[buf][kk][tx << 2];
            u64 ip[4] = {aL.x, aL.y, aH.x, aH.y};
            u64 jd[4] = {dup2(jv.x), dup2(jv.y), dup2(jv.z), dup2(jv.w)};
            u64 wd = dup2(w2s[d0 + kk]);
            #pragma unroll
            for (int p = 0; p < 4; p++)
                #pragma unroll
                for (int j = 0; j < 4; j++)
                    fma2(acc[p][j], relu2(add2(ip[p], jd[j])), wd);
        }

        if (more) {
            int nb = buf ^ 1;
            His[nb][ac0 + 0][ar0] = i0.x; His[nb][ac0 + 1][ar0] = i0.y;
            His[nb][ac0 + 2][ar0] = i0.z; His[nb][ac0 + 3][ar0] = i0.w;
            His[nb][ac1 + 0][ar1] = i1.x; His[nb][ac1 + 1][ar1] = i1.y;
            His[nb][ac1 + 2][ar1] = i1.z; His[nb][ac1 + 3][ar1] = i1.w;
            Hjs[nb][ac0 + 0][ar0] = j0.x; Hjs[nb][ac0 + 1][ar0] = j0.y;
            Hjs[nb][ac0 + 2][ar0] = j0.z; Hjs[nb][ac0 + 3][ar0] = j0.w;
            Hjs[nb][ac1 + 0][ar1] = j1.x; Hjs[nb][ac1 + 1][ar1] = j1.y;
            Hjs[nb][ac1 + 2][ar1] = j1.z; Hjs[nb][ac1 + 3][ar1] = j1.w;
        }
        __syncthreads();
        buf ^= 1;
    }

    const float b2v = b2[0];
    float* sc = g_sc + (long)b * NN * NN;
    int n0 = nBase + (tyg << 3);
    int m0 = mBase + (tx << 2);

    #pragma unroll
    for (int p = 0; p < 4; p++) {
        float e0, o0, e1, o1, e2, o2, e3, o3;
        unpack2(acc[p][0], e0, o0); unpack2(acc[p][1], e1, o1);
        unpack2(acc[p][2], e2, o2); unpack2(acc[p][3], e3, o3);
        int nE = n0 + 2 * p, nO = nE + 1;
        float4 vE = make_float4(
            (nE == m0 + 0) ? 0.0f : e0 + b2v, (nE == m0 + 1) ? 0.0f : e1 + b2v,
            (nE == m0 + 2) ? 0.0f : e2 + b2v, (nE == m0 + 3) ? 0.0f : e3 + b2v);
        float4 vO = make_float4(
            (nO == m0 + 0) ? 0.0f : o0 + b2v, (nO == m0 + 1) ? 0.0f : o1 + b2v,
            (nO == m0 + 2) ? 0.0f : o2 + b2v, (nO == m0 + 3) ? 0.0f : o3 + b2v);
        *(float4*)&sc[(long)nE * NN + m0] = vE;
        *(float4*)&sc[(long)nO * NN + m0] = vO;
    }
}

// ---------------- softmax over m, in place on g_sc ----------------
__global__ void softmax_k()
{
    __shared__ float red[8];
    int row = blockIdx.x;          // b*N + n
    int tid = threadIdx.x;
    int wid = tid >> 5, lane = tid & 31;

    float* sc = g_sc + (long)row * NN;
    float v = sc[tid];

    float mv = v;
    #pragma unroll
    for (int o = 16; o > 0; o >>= 1) mv = fmaxf(mv, __shfl_xor_sync(0xffffffffu, mv, o));
    if (lane == 0) red[wid] = mv;
    __syncthreads();
    float mx = red[0];
    #pragma unroll
    for (int w = 1; w < 8; w++) mx = fmaxf(mx, red[w]);

    float e = __expf(v - mx);
    float s = e;
    #pragma unroll
    for (int o = 16; o > 0; o >>= 1) s += __shfl_xor_sync(0xffffffffu, s, o);
    __syncthreads();
    if (lane == 0) red[wid] = s;
    __syncthreads();
    float sum = 0.0f;
    #pragma unroll
    for (int w = 0; w < 8; w++) sum += red[w];

    sc[tid] = e * (1.0f / sum);
}

// ---------------- LayerNorm + residual ----------------
__global__ void ln_res_k(const float* __restrict__ x,
                         const float* __restrict__ gamma,
                         const float* __restrict__ beta,
                         float* __restrict__ out)
{
    __shared__ float red[8];
    int row = blockIdx.x;
    int tid = threadIdx.x;
    int wid = tid >> 5, lane = tid & 31;

    float p = g_proj[(long)row * DD + tid];

    float s = p;
    #pragma unroll
    for (int o = 16; o > 0; o >>= 1) s += __shfl_xor_sync(0xffffffffu, s, o);
    if (lane == 0) red[wid] = s;
    __syncthreads();
    float tot = 0.0f;
    #pragma unroll
    for (int w = 0; w < 8; w++) tot += red[w];
    float mean = tot * (1.0f / DD);

    float dv = p - mean;
    float q = dv * dv;
    #pragma unroll
    for (int o = 16; o > 0; o >>= 1) q += __shfl_xor_sync(0xffffffffu, q, o);
    __syncthreads();
    if (lane == 0) red[wid] = q;
    __syncthreads();
    float tq = 0.0f;
    #pragma unroll
    for (int w = 0; w < 8; w++) tq += red[w];
    float var = tq * (1.0f / DD);

    float inv = rsqrtf(var + LN_EPS);
    out[(long)row * DD + tid] = x[(long)row * DD + tid] + dv * inv * gamma[tid] + beta[tid];
}

// ---------------- launch ----------------
extern "C" void kernel_launch(void* const* d_in, const int* in_sizes, int n_in,
                              void* d_out, int out_size)
{
    const float* x     = (const float*)d_in[0];  // [B,N,D]
    const float* W1    = (const float*)d_in[1];  // [2D,D]
    const float* b1    = (const float*)d_in[2];  // [D]
    const float* W2    = (const float*)d_in[3];  // [D,1]
    const float* b2    = (const float*)d_in[4];  // [1]
    const float* Wp    = (const float*)d_in[5];  // [D,D]
    const float* bp    = (const float*)d_in[6];  // [D]
    const float* gamma = (const float*)d_in[7];  // [D]
    const float* beta  = (const float*)d_in[8];  // [D]
    float* out = (float*)d_out;

    float *hihj, *sc, *ctx, *proj;
    cudaGetSymbolAddress((void**)&hihj, g_hihj);
    cudaGetSymbolAddress((void**)&sc,   g_sc);
    cudaGetSymbolAddress((void**)&ctx,  g_ctx);
    cudaGetSymbolAddress((void**)&proj, g_proj);

    // 1) hi' = x @ W1[:D] + 0.5*b1 ; hj' = x @ W1[D:] + 0.5*b1
    gemm_k<<<dim3((BSZ * NN) / 64, DD / 64, 2), 128>>>(
        x, 0L, W1, (long)DD * DD, hihj, (long)BSZ * NN * DD,
        b1, 0.5f, DD, DD);

    // 2) pairwise relu scores (+b2, diag=0)
    scores_k<<<dim3(NN / 64, NN / 64, BSZ), 128>>>(W2, b2);

    // 3) softmax over m (in place)
    softmax_k<<<BSZ * NN, 256>>>();

    // 4) ctx[b] = weights[b] @ x[b]
    gemm_k<<<dim3(NN / 64, DD / 64, BSZ), 128>>>(
        sc, (long)NN * NN, x, (long)NN * DD, ctx, (long)NN * DD,
        nullptr, 0.0f, NN, DD);

    // 5) proj = ctx @ Wp + bp
    gemm_k<<<dim3((BSZ * NN) / 64, DD / 64, 1), 128>>>(
        ctx, 0L, Wp, 0L, proj, 0L,
        bp, 1.0f, DD, DD);

    // 6) out = x + LN(proj)
    ln_res_k<<<BSZ * NN, 256>>>(x, gamma, beta, out);
}

// round 6
// speedup vs baseline: 1.3346x; 1.2702x over previous
#include <cuda_runtime.h>
#include <cuda_bf16.h>
#include <cstdint>

#define BSZ 8
#define NN  256
#define DD  256
#define LN_EPS 1e-5f

// ---------------- scratch (no allocation allowed) ----------------
__device__ __align__(16) float g_hihj[2 * BSZ * NN * DD];   // hi+0.5*b1, hj+0.5*b1
__device__ __align__(16) float g_sc  [BSZ * NN * NN];       // raw scores (diag=0, +b2)
__device__ __align__(16) float g_ctx [BSZ * NN * DD];
__device__ __align__(16) float g_proj[BSZ * NN * DD];

// ---------------- f32x2 helpers (exact fp32, packed pipe) ----------------
typedef unsigned long long u64;

__device__ __forceinline__ u64 dup2(float x) {
    u64 r; asm("mov.b64 %0, {%1, %2};" : "=l"(r) : "f"(x), "f"(x)); return r;
}
__device__ __forceinline__ void fma2(u64& a, u64 b, u64 c) {
    asm("fma.rn.f32x2 %0, %1, %2, %0;" : "+l"(a) : "l"(b), "l"(c));
}
__device__ __forceinline__ u64 add2(u64 a, u64 b) {
    u64 r; asm("add.rn.f32x2 %0, %1, %2;" : "=l"(r) : "l"(a), "l"(b)); return r;
}
__device__ __forceinline__ void unpack2(u64 v, float& lo, float& hi) {
    asm("mov.b64 {%0, %1}, %2;" : "=f"(lo), "=f"(hi) : "l"(v));
}
__device__ __forceinline__ u64 relu2(u64 v) {
    float lo, hi;
    asm("mov.b64 {%0, %1}, %2;" : "=f"(lo), "=f"(hi) : "l"(v));
    lo = fmaxf(lo, 0.0f); hi = fmaxf(hi, 0.0f);
    u64 r; asm("mov.b64 %0, {%1, %2};" : "=l"(r) : "f"(lo), "f"(hi));
    return r;
}

#define APAD 68   // padded row for transposed A-stage (keeps 16B alignment, halves store conflicts)

// ---------------- GEMM: C = A @ W (+ bias*bscale) ----------------
// Tile 64x64x16, 256 threads, micro 4x4 (2 f32x2 row-pairs x 4 cols).
__global__ void __launch_bounds__(256) gemm_k(
    const float* __restrict__ A, long sA,
    const float* __restrict__ W, long sW,
    float* __restrict__ C, long sC,
    const float* __restrict__ bias, float bscale,
    int K, int Ncol)
{
    const int BK = 16;
    __shared__ __align__(16) float As[2][BK][APAD];   // transposed: As[k][m]
    __shared__ __align__(16) float Ws[2][BK][64];     // Ws[k][n]

    int z = blockIdx.z;
    A += (long)z * sA;  W += (long)z * sW;  C += (long)z * sC;

    int tid = threadIdx.x;
    int tx  = tid & 15;        // col group: cols tx*4..+3
    int tyr = tid >> 4;        // 0..15 row group: rows tyr*4..+3
    int rowBase = blockIdx.x * 64;
    int colBase = blockIdx.y * 64;

    int ar = tid >> 2, ac = (tid & 3) << 2;   // A loader: 64x16 tile, 1 float4/thread
    int wr = tid >> 4, wc = (tid & 15) << 2;  // W loader: 16x64 tile, 1 float4/thread

    u64 acc[2][4] = {};

    float4 av = *(const float4*)&A[(long)(rowBase + ar) * K + ac];
    float4 wv = *(const float4*)&W[(long)wr * Ncol + colBase + wc];
    As[0][ac + 0][ar] = av.x; As[0][ac + 1][ar] = av.y;
    As[0][ac + 2][ar] = av.z; As[0][ac + 3][ar] = av.w;
    *(float4*)&Ws[0][wr][wc] = wv;
    __syncthreads();

    int buf = 0;
    for (int k0 = 0; k0 < K; k0 += BK) {
        bool more = (k0 + BK) < K;
        if (more) {
            av = *(const float4*)&A[(long)(rowBase + ar) * K + k0 + BK + ac];
            wv = *(const float4*)&W[(long)(k0 + BK + wr) * Ncol + colBase + wc];
        }

        #pragma unroll
        for (int kk = 0; kk < BK; kk++) {
            ulonglong2 a = *(const ulonglong2*)&As[buf][kk][tyr << 2];
            float4 w4 = *(const float4*)&Ws[buf][kk][tx << 2];
            u64 wd[4] = {dup2(w4.x), dup2(w4.y), dup2(w4.z), dup2(w4.w)};
            #pragma unroll
            for (int j = 0; j < 4; j++) {
                fma2(acc[0][j], a.x, wd[j]);
                fma2(acc[1][j], a.y, wd[j]);
            }
        }

        if (more) {
            int nb = buf ^ 1;
            As[nb][ac + 0][ar] = av.x; As[nb][ac + 1][ar] = av.y;
            As[nb][ac + 2][ar] = av.z; As[nb][ac + 3][ar] = av.w;
            *(float4*)&Ws[nb][wr][wc] = wv;
        }
        __syncthreads();
        buf ^= 1;
    }

    int row0 = rowBase + (tyr << 2);
    int col  = colBase + (tx << 2);
    float4 bv = make_float4(0.f, 0.f, 0.f, 0.f);
    if (bias) {
        bv = *(const float4*)&bias[col];
        bv.x *= bscale; bv.y *= bscale; bv.z *= bscale; bv.w *= bscale;
    }

    #pragma unroll
    for (int p = 0; p < 2; p++) {
        float e0, o0, e1, o1, e2, o2, e3, o3;
        unpack2(acc[p][0], e0, o0); unpack2(acc[p][1], e1, o1);
        unpack2(acc[p][2], e2, o2); unpack2(acc[p][3], e3, o3);
        *(float4*)&C[(long)(row0 + 2 * p + 0) * Ncol + col] =
            make_float4(e0 + bv.x, e1 + bv.y, e2 + bv.z, e3 + bv.w);
        *(float4*)&C[(long)(row0 + 2 * p + 1) * Ncol + col] =
            make_float4(o0 + bv.x, o1 + bv.y, o2 + bv.z, o3 + bv.w);
    }
}

// ---------------- pairwise relu score kernel ----------------
// scores[b,n,m] = sum_d relu(hi'[n,d] + hj'[m,d]) * W2[d] + b2   (b1 pre-folded)
// Tile 64x64x16, 256 threads, micro 4x4.
__global__ void __launch_bounds__(256) scores_k(
    const float* __restrict__ W2,
    const float* __restrict__ b2)
{
    const int DK = 16;
    __shared__ __align__(16) float His[2][DK][APAD];  // [d][n]
    __shared__ __align__(16) float Hjs[2][DK][64];    // [d][m]
    __shared__ float w2s[DD];

    int b = blockIdx.z;
    int mBase = blockIdx.x * 64;
    int nBase = blockIdx.y * 64;
    int tid = threadIdx.x;
    int tx  = tid & 15;
    int tyr = tid >> 4;

    const float* hi = g_hihj + (long)b * NN * DD;
    const float* hj = g_hihj + (long)BSZ * NN * DD + (long)b * NN * DD;

    w2s[tid] = W2[tid];   // 256 threads cover D=256

    int ar = tid >> 2, ac = (tid & 3) << 2;
    int jr = tid >> 4, jc = (tid & 15) << 2;   // hj staged like W: [d][m], read per-d

    u64 acc[2][4] = {};

    float4 iv = *(const float4*)&hi[(long)(nBase + ar) * DD + ac];
    // hj needs transposed staging too: load 64x16 of hj, store to Hjs[d][m]
    float4 jv = *(const float4*)&hj[(long)(mBase + ar) * DD + ac];
    His[0][ac + 0][ar] = iv.x; His[0][ac + 1][ar] = iv.y;
    His[0][ac + 2][ar] = iv.z; His[0][ac + 3][ar] = iv.w;
    Hjs[0][ac + 0][ar] = jv.x; Hjs[0][ac + 1][ar] = jv.y;
    Hjs[0][ac + 2][ar] = jv.z; Hjs[0][ac + 3][ar] = jv.w;
    __syncthreads();

    int buf = 0;
    for (int d0 = 0; d0 < DD; d0 += DK) {
        bool more = (d0 + DK) < DD;
        if (more) {
            iv = *(const float4*)&hi[(long)(nBase + ar) * DD + d0 + DK + ac];
            jv = *(const float4*)&hj[(long)(mBase + ar) * DD + d0 + DK + ac];
        }

        #pragma unroll
        for (int kk = 0; kk < DK; kk++) {
            ulonglong2 a = *(const ulonglong2*)&His[buf][kk][tyr << 2];
            float4 j4 = *(const float4*)&Hjs[buf][kk][tx << 2];
            u64 jd[4] = {dup2(j4.x), dup2(j4.y), dup2(j4.z), dup2(j4.w)};
            u64 wd = dup2(w2s[d0 + kk]);
            #pragma unroll
            for (int j = 0; j < 4; j++) {
                fma2(acc[0][j], relu2(add2(a.x, jd[j])), wd);
                fma2(acc[1][j], relu2(add2(a.y, jd[j])), wd);
            }
        }

        if (more) {
            int nb = buf ^ 1;
            His[nb][ac + 0][ar] = iv.x; His[nb][ac + 1][ar] = iv.y;
            His[nb][ac + 2][ar] = iv.z; His[nb][ac + 3][ar] = iv.w;
            Hjs[nb][ac + 0][ar] = jv.x; Hjs[nb][ac + 1][ar] = jv.y;
            Hjs[nb][ac + 2][ar] = jv.z; Hjs[nb][ac + 3][ar] = jv.w;
        }
        __syncthreads();
        buf ^= 1;
    }

    const float b2v = b2[0];
    float* sc = g_sc + (long)b * NN * NN;
    int n0 = nBase + (tyr << 2);
    int m0 = mBase + (tx << 2);

    #pragma unroll
    for (int p = 0; p < 2; p++) {
        float e0, o0, e1, o1, e2, o2, e3, o3;
        unpack2(acc[p][0], e0, o0); unpack2(acc[p][1], e1, o1);
        unpack2(acc[p][2], e2, o2); unpack2(acc[p][3], e3, o3);
        int nE = n0 + 2 * p, nO = nE + 1;
        float4 vE = make_float4(
            (nE == m0 + 0) ? 0.0f : e0 + b2v, (nE == m0 + 1) ? 0.0f : e1 + b2v,
            (nE == m0 + 2) ? 0.0f : e2 + b2v, (nE == m0 + 3) ? 0.0f : e3 + b2v);
        float4 vO = make_float4(
            (nO == m0 + 0) ? 0.0f : o0 + b2v, (nO == m0 + 1) ? 0.0f : o1 + b2v,
            (nO == m0 + 2) ? 0.0f : o2 + b2v, (nO == m0 + 3) ? 0.0f : o3 + b2v);
        *(float4*)&sc[(long)nE * NN + m0] = vE;
        *(float4*)&sc[(long)nO * NN + m0] = vO;
    }
}

// ---------------- fused softmax + ctx GEMM ----------------
// ctx[b,n,:] = softmax_m(sc[b,n,:]) @ x[b]   computed as (sum_m e[n,m] x[m,:]) * inv[n]
__global__ void __launch_bounds__(256) ctx_k(const float* __restrict__ x)
{
    const int BK = 16;
    __shared__ __align__(16) float As[2][BK][APAD];
    __shared__ __align__(16) float Ws[2][BK][64];
    __shared__ float mxs[64], invs[64];

    int b = blockIdx.z;
    int nBase = blockIdx.x * 64;
    int colBase = blockIdx.y * 64;
    int tid = threadIdx.x;
    int tx  = tid & 15;
    int tyr = tid >> 4;
    int wid = tid >> 5, lane = tid & 31;

    const float* sc = g_sc + (long)b * NN * NN;
    const float* X  = x + (long)b * NN * DD;

    // phase 0: per-row max & 1/sum(exp) for the 64 n-rows of this tile
    #pragma unroll
    for (int rr = 0; rr < 8; rr++) {
        int r = wid * 8 + rr;
        const float* row = sc + (long)(nBase + r) * NN;
        float4 v0 = *(const float4*)&row[lane * 8];
        float4 v1 = *(const float4*)&row[lane * 8 + 4];
        float mx = fmaxf(fmaxf(fmaxf(v0.x, v0.y), fmaxf(v0.z, v0.w)),
                         fmaxf(fmaxf(v1.x, v1.y), fmaxf(v1.z, v1.w)));
        #pragma unroll
        for (int o = 16; o > 0; o >>= 1) mx = fmaxf(mx, __shfl_xor_sync(0xffffffffu, mx, o));
        float s = __expf(v0.x - mx) + __expf(v0.y - mx) + __expf(v0.z - mx) + __expf(v0.w - mx)
                + __expf(v1.x - mx) + __expf(v1.y - mx) + __expf(v1.z - mx) + __expf(v1.w - mx);
        #pragma unroll
        for (int o = 16; o > 0; o >>= 1) s += __shfl_xor_sync(0xffffffffu, s, o);
        if (lane == 0) { mxs[r] = mx; invs[r] = 1.0f / s; }
    }
    __syncthreads();

    int ar = tid >> 2, ac = (tid & 3) << 2;
    int wr = tid >> 4, wc = (tid & 15) << 2;
    float rmx = mxs[ar];

    u64 acc[2][4] = {};

    float4 av = *(const float4*)&sc[(long)(nBase + ar) * NN + ac];
    float4 wv = *(const float4*)&X[(long)wr * DD + colBase + wc];
    As[0][ac + 0][ar] = __expf(av.x - rmx); As[0][ac + 1][ar] = __expf(av.y - rmx);
    As[0][ac + 2][ar] = __expf(av.z - rmx); As[0][ac + 3][ar] = __expf(av.w - rmx);
    *(float4*)&Ws[0][wr][wc] = wv;
    __syncthreads();

    int buf = 0;
    for (int k0 = 0; k0 < NN; k0 += BK) {
        bool more = (k0 + BK) < NN;
        if (more) {
            av = *(const float4*)&sc[(long)(nBase + ar) * NN + k0 + BK + ac];
            wv = *(const float4*)&X[(long)(k0 + BK + wr) * DD + colBase + wc];
        }

        #pragma unroll
        for (int kk = 0; kk < BK; kk++) {
            ulonglong2 a = *(const ulonglong2*)&As[buf][kk][tyr << 2];
            float4 w4 = *(const float4*)&Ws[buf][kk][tx << 2];
            u64 wd[4] = {dup2(w4.x), dup2(w4.y), dup2(w4.z), dup2(w4.w)};
            #pragma unroll
            for (int j = 0; j < 4; j++) {
                fma2(acc[0][j], a.x, wd[j]);
                fma2(acc[1][j], a.y, wd[j]);
            }
        }

        if (more) {
            int nb = buf ^ 1;
            As[nb][ac + 0][ar] = __expf(av.x - rmx); As[nb][ac + 1][ar] = __expf(av.y - rmx);
            As[nb][ac + 2][ar] = __expf(av.z - rmx); As[nb][ac + 3][ar] = __expf(av.w - rmx);
            *(float4*)&Ws[nb][wr][wc] = wv;
        }
        __syncthreads();
        buf ^= 1;
    }

    float* ctx = g_ctx + (long)b * NN * DD;
    int r0 = (tyr << 2);
    int col = colBase + (tx << 2);
    #pragma unroll
    for (int p = 0; p < 2; p++) {
        float e0, o0, e1, o1, e2, o2, e3, o3;
        unpack2(acc[p][0], e0, o0); unpack2(acc[p][1], e1, o1);
        unpack2(acc[p][2], e2, o2); unpack2(acc[p][3], e3, o3);
        float iE = invs[r0 + 2 * p], iO = invs[r0 + 2 * p + 1];
        *(float4*)&ctx[(long)(nBase + r0 + 2 * p + 0) * DD + col] =
            make_float4(e0 * iE, e1 * iE, e2 * iE, e3 * iE);
        *(float4*)&ctx[(long)(nBase + r0 + 2 * p + 1) * DD + col] =
            make_float4(o0 * iO, o1 * iO, o2 * iO, o3 * iO);
    }
}

// ---------------- LayerNorm + residual ----------------
__global__ void ln_res_k(const float* __restrict__ x,
                         const float* __restrict__ gamma,
                         const float* __restrict__ beta,
                         float* __restrict__ out)
{
    __shared__ float red[8];
    int row = blockIdx.x;
    int tid = threadIdx.x;
    int wid = tid >> 5, lane = tid & 31;

    float p = g_proj[(long)row * DD + tid];

    float s = p;
    #pragma unroll
    for (int o = 16; o > 0; o >>= 1) s += __shfl_xor_sync(0xffffffffu, s, o);
    if (lane == 0) red[wid] = s;
    __syncthreads();
    float tot = 0.0f;
    #pragma unroll
    for (int w = 0; w < 8; w++) tot += red[w];
    float mean = tot * (1.0f / DD);

    float dv = p - mean;
    float q = dv * dv;
    #pragma unroll
    for (int o = 16; o > 0; o >>= 1) q += __shfl_xor_sync(0xffffffffu, q, o);
    __syncthreads();
    if (lane == 0) red[wid] = q;
    __syncthreads();
    float tq = 0.0f;
    #pragma unroll
    for (int w = 0; w < 8; w++) tq += red[w];
    float var = tq * (1.0f / DD);

    float inv = rsqrtf(var + LN_EPS);
    out[(long)row * DD + tid] = x[(long)row * DD + tid] + dv * inv * gamma[tid] + beta[tid];
}

// ---------------- launch ----------------
extern "C" void kernel_launch(void* const* d_in, const int* in_sizes, int n_in,
                              void* d_out, int out_size)
{
    const float* x     = (const float*)d_in[0];  // [B,N,D]
    const float* W1    = (const float*)d_in[1];  // [2D,D]
    const float* b1    = (const float*)d_in[2];  // [D]
    const float* W2    = (const float*)d_in[3];  // [D,1]
    const float* b2    = (const float*)d_in[4];  // [1]
    const float* Wp    = (const float*)d_in[5];  // [D,D]
    const float* bp    = (const float*)d_in[6];  // [D]
    const float* gamma = (const float*)d_in[7];  // [D]
    const float* beta  = (const float*)d_in[8];  // [D]
    float* out = (float*)d_out;

    float *hihj, *ctx, *proj;
    cudaGetSymbolAddress((void**)&hihj, g_hihj);
    cudaGetSymbolAddress((void**)&ctx,  g_ctx);
    cudaGetSymbolAddress((void**)&proj, g_proj);

    // 1) hi' = x @ W1[:D] + 0.5*b1 ; hj' = x @ W1[D:] + 0.5*b1
    gemm_k<<<dim3((BSZ * NN) / 64, DD / 64, 2), 256>>>(
        x, 0L, W1, (long)DD * DD, hihj, (long)BSZ * NN * DD,
        b1, 0.5f, DD, DD);

    // 2) pairwise relu scores (+b2, diag=0)
    scores_k<<<dim3(NN / 64, NN / 64, BSZ), 256>>>(W2, b2);

    // 3+4) fused softmax + ctx GEMM
    ctx_k<<<dim3(NN / 64, DD / 64, BSZ), 256>>>(x);

    // 5) proj = ctx @ Wp + bp
    gemm_k<<<dim3((BSZ * NN) / 64, DD / 64, 1), 256>>>(
        ctx, 0L, Wp, 0L, proj, 0L,
        bp, 1.0f, DD, DD);

    // 6) out = x + LN(proj)
    ln_res_k<<<BSZ * NN, 256>>>(x, gamma, beta, out);
}